// round 4
// baseline (speedup 1.0000x reference)
#include <cuda_runtime.h>
#include <cuda_fp16.h>
#include <math.h>
#include <stdint.h>

#define N_TOK 4096
#define DIMSZ 1024
#define NEXP  8
#define HID   4096
#define EPSV  1e-6f
#define MAX_BLK 24        // sum ceil(c_e/256) <= 16 + 8

// tiling
#define BM   256
#define BN   128
#define KC   32
#define NSTG 3
// dynamic smem layout (bytes)
#define AS_STG   (256 * 80)          // 256 rows x 40 halves
#define BS_STG   (32 * 136 * 2)      // 32 rows x 136 halves (R0 layout)
#define BSTG_STG (32 * 528)          // 32 rows x 132 floats staging
#define OFF_AS   0
#define OFF_BS   (NSTG * AS_STG)                 // 61440
#define OFF_BSTG (OFF_BS + NSTG * BS_STG)        // 87552
#define SMEM_TOT (OFF_BSTG + NSTG * BSTG_STG)    // 138240

// ---------------- scratch ----------------
__device__ float  g_gateval[N_TOK];
__device__ int    g_expert[N_TOK];
__device__ float  g_weight[N_TOK];
__device__ float  g_denom[NEXP];
__device__ int    g_counts[NEXP];
__device__ int    g_cursor[NEXP];
__device__ int    g_perm[N_TOK];
__device__ __half g_xg[(size_t)(N_TOK + BM) * DIMSZ];  // gathered x fp16 (+pad rows, stay 0)
__device__ __half g_h[(size_t)(N_TOK + BM) * HID];     // gelu(x@W1) fp16 (+pad rows)
__device__ int    g_blk_expert[MAX_BLK];
__device__ int    g_blk_start[MAX_BLK];
__device__ int    g_blk_rows[MAX_BLK];
__device__ int    g_nblk;

__device__ __forceinline__ uint32_t s2u(const void* p) {
    return (uint32_t)__cvta_generic_to_shared(p);
}
__device__ __forceinline__ void cp16(uint32_t s, const void* g) {
    asm volatile("cp.async.cg.shared.global [%0], [%1], 16;\n" :: "r"(s), "l"(g));
}
#define CP_COMMIT() asm volatile("cp.async.commit_group;\n" ::: "memory")
#define CP_WAIT0()  asm volatile("cp.async.wait_group 0;\n" ::: "memory")
#define CP_WAIT1()  asm volatile("cp.async.wait_group 1;\n" ::: "memory")

// ---------------- kernel 0: reset ----------------
__global__ void init_kernel() {
    int t = threadIdx.x;
    if (t < NEXP) { g_denom[t] = 0.f; g_counts[t] = 0; }
}

// ---------------- kernel 1: gate ----------------
__global__ void gate_kernel(const float* __restrict__ x,
                            const float* __restrict__ wg,
                            const float* __restrict__ bg) {
    int warp = threadIdx.x >> 5, lane = threadIdx.x & 31;
    int t = blockIdx.x * 8 + warp;
    if (t >= N_TOK) return;
    const float* xr = x + (size_t)t * DIMSZ;
    float acc[NEXP];
#pragma unroll
    for (int e = 0; e < NEXP; e++) acc[e] = 0.f;
    for (int k = lane; k < DIMSZ; k += 32) {
        float xv = __ldg(xr + k);
        const float* wr = wg + (size_t)k * NEXP;
#pragma unroll
        for (int e = 0; e < NEXP; e++) acc[e] = fmaf(xv, __ldg(wr + e), acc[e]);
    }
#pragma unroll
    for (int e = 0; e < NEXP; e++)
#pragma unroll
        for (int o = 16; o > 0; o >>= 1)
            acc[e] += __shfl_xor_sync(0xFFFFFFFFu, acc[e], o);
    if (lane == 0) {
#pragma unroll
        for (int e = 0; e < NEXP; e++) acc[e] += bg[e];
        int top = 0; float best = acc[0];
#pragma unroll
        for (int e = 1; e < NEXP; e++) if (acc[e] > best) { best = acc[e]; top = e; }
        float s = 0.f;
#pragma unroll
        for (int e = 0; e < NEXP; e++) s += expf(acc[e] - best);
        float gv = 1.0f / s;
        g_gateval[t] = gv;
        g_expert[t]  = top;
        atomicAdd(&g_denom[top], gv);
        atomicAdd(&g_counts[top], 1);
    }
}

// ---------------- kernel 2: route ----------------
__global__ void route_kernel() {
    int tid = threadIdx.x;
    if (tid == 0) {
        int acc = 0, nb = 0;
        for (int e = 0; e < NEXP; e++) {
            g_cursor[e] = acc;
            int c = g_counts[e];
            for (int s = 0; s < c; s += BM) {
                g_blk_expert[nb] = e;
                g_blk_start[nb]  = acc + s;
                g_blk_rows[nb]   = min(BM, c - s);
                nb++;
            }
            acc += c;
        }
        g_nblk = nb;
    }
    __syncthreads();
    for (int t = tid; t < N_TOK; t += blockDim.x) {
        int e = g_expert[t];
        int pos = atomicAdd(&g_cursor[e], 1);
        g_perm[pos] = t;
        g_weight[t] = g_gateval[t] / (g_denom[e] + EPSV) * (float)N_TOK;
    }
}

// ---------------- kernel 3: gather ----------------
__global__ void gather_kernel(const float* __restrict__ x) {
    int i = blockIdx.x;
    int t = g_perm[i];
    const float4* src = (const float4*)(x + (size_t)t * DIMSZ);
    __half2* dst = (__half2*)(g_xg + (size_t)i * DIMSZ);
    for (int j = threadIdx.x; j < DIMSZ / 4; j += blockDim.x) {
        float4 v = src[j];
        dst[j * 2 + 0] = __floats2half2_rn(v.x, v.y);
        dst[j * 2 + 1] = __floats2half2_rn(v.z, v.w);
    }
}

// ---------------- grouped GEMM: 256x128 tile, cp.async 3-stage, mma.sync ----
// PHASE 1: A=g_xg [*,1024], B=W1 fp32 -> gelu -> g_h fp16
// PHASE 2: A=g_h  [*,4096], B=W2 fp32 -> *weight -> scatter out fp32
template <int KDIM, int NDIM, int PHASE>
__global__ void __launch_bounds__(256, 1) moe_gemm(
    const float* __restrict__ Bglob,
    const float* __restrict__ bias,
    float* __restrict__ out)
{
    int blk = blockIdx.x;
    if (blk >= g_nblk) return;
    const int e    = g_blk_expert[blk];
    const int s    = g_blk_start[blk];
    const int rows = g_blk_rows[blk];
    const int n0   = blockIdx.y * BN;

    extern __shared__ __align__(16) char dynsmem[];
    const uint32_t as_u   = s2u(dynsmem) + OFF_AS;
    const uint32_t bs_u   = s2u(dynsmem) + OFF_BS;
    const uint32_t bstg_u = s2u(dynsmem) + OFF_BSTG;

    const int tid  = threadIdx.x;
    const int warp = tid >> 5, lane = tid & 31;
    const int wm = warp >> 1;      // 0..3 -> m offset wm*64
    const int wn = warp & 1;       // 0..1 -> n offset wn*64

    const __half* A = (PHASE == 1 ? g_xg : g_h) + (size_t)s * KDIM;
    const float*  B = Bglob + (size_t)e * KDIM * NDIM + n0;

    float acc[4][8][4];
#pragma unroll
    for (int a = 0; a < 4; a++)
#pragma unroll
        for (int b = 0; b < 8; b++)
#pragma unroll
            for (int c = 0; c < 4; c++) acc[a][b][c] = 0.f;

    auto load_stage = [&](int stg, int slot) {
        const int k0 = stg * KC;
        // A: 256 rows x 32 halves = 1024 x 16B chunks
        const __half* Ap = A + k0;
#pragma unroll
        for (int it = 0; it < 4; it++) {
            int id = it * 256 + tid;
            int r = id >> 2, c = id & 3;
            cp16(as_u + slot * AS_STG + r * 80 + c * 16,
                 Ap + (size_t)r * KDIM + c * 8);
        }
        // B staging: 32 rows x 128 floats = 1024 x 16B chunks
        const float* Bp = B + (size_t)k0 * NDIM;
#pragma unroll
        for (int it = 0; it < 4; it++) {
            int id = it * 256 + tid;
            int r = id >> 5, c = id & 31;
            cp16(bstg_u + slot * BSTG_STG + r * 528 + c * 16,
                 Bp + (size_t)r * NDIM + c * 4);
        }
        CP_COMMIT();
    };

    auto convert_b = [&](int slot) {
        const float* src = (const float*)(dynsmem + OFF_BSTG + slot * BSTG_STG);
        __half* dst = (__half*)(dynsmem + OFF_BS + slot * BS_STG);
#pragma unroll
        for (int it = 0; it < 4; it++) {
            int id = it * 256 + tid;
            int r = id >> 5, c4 = id & 31;
            float4 v = *(const float4*)(src + r * 132 + c4 * 4);
            __half2* d = (__half2*)(dst + r * 136 + c4 * 4);
            d[0] = __floats2half2_rn(v.x, v.y);
            d[1] = __floats2half2_rn(v.z, v.w);
        }
    };

    // prologue
    load_stage(0, 0);
    load_stage(1, 1);

    const int nk = KDIM / KC;
    for (int k = 0; k < nk; k++) {
        const int slot = k % NSTG;
        if (k == nk - 1) { CP_WAIT0(); } else { CP_WAIT1(); }
        __syncthreads();
        convert_b(slot);
        if (k + 2 < nk) load_stage(k + 2, (k + 2) % NSTG);
        __syncthreads();

        const uint32_t abase = as_u + slot * AS_STG;
        const uint32_t bbase = bs_u + slot * BS_STG;
#pragma unroll
        for (int ks = 0; ks < 2; ks++) {
            const int kk = ks * 16;
            uint32_t afr[4][4];
#pragma unroll
            for (int mt = 0; mt < 4; mt++) {
                int r = wm * 64 + mt * 16 + (lane & 7) + ((lane >> 3) & 1) * 8;
                int c = kk + (lane >> 4) * 8;
                uint32_t addr = abase + r * 80 + c * 2;
                asm volatile("ldmatrix.sync.aligned.m8n8.x4.shared.b16 {%0,%1,%2,%3}, [%4];\n"
                             : "=r"(afr[mt][0]), "=r"(afr[mt][1]),
                               "=r"(afr[mt][2]), "=r"(afr[mt][3])
                             : "r"(addr));
            }
            uint32_t bfr[8][2];
#pragma unroll
            for (int q = 0; q < 4; q++) {
                int mi = lane >> 3;
                int kr = kk + (mi & 1) * 8 + (lane & 7);
                int nc = wn * 64 + q * 16 + (mi >> 1) * 8;
                uint32_t addr = bbase + (kr * 136 + nc) * 2;
                uint32_t r0, r1, r2, r3;
                asm volatile("ldmatrix.sync.aligned.m8n8.x4.trans.shared.b16 {%0,%1,%2,%3}, [%4];\n"
                             : "=r"(r0), "=r"(r1), "=r"(r2), "=r"(r3)
                             : "r"(addr));
                bfr[q * 2 + 0][0] = r0; bfr[q * 2 + 0][1] = r1;
                bfr[q * 2 + 1][0] = r2; bfr[q * 2 + 1][1] = r3;
            }
#pragma unroll
            for (int mt = 0; mt < 4; mt++)
#pragma unroll
                for (int nf = 0; nf < 8; nf++) {
                    asm volatile(
                        "mma.sync.aligned.m16n8k16.row.col.f32.f16.f16.f32 "
                        "{%0,%1,%2,%3}, {%4,%5,%6,%7}, {%8,%9}, {%0,%1,%2,%3};\n"
                        : "+f"(acc[mt][nf][0]), "+f"(acc[mt][nf][1]),
                          "+f"(acc[mt][nf][2]), "+f"(acc[mt][nf][3])
                        : "r"(afr[mt][0]), "r"(afr[mt][1]),
                          "r"(afr[mt][2]), "r"(afr[mt][3]),
                          "r"(bfr[nf][0]), "r"(bfr[nf][1]));
                }
        }
        __syncthreads();
    }

    // ---------------- epilogue ----------------
#pragma unroll
    for (int mt = 0; mt < 4; mt++) {
#pragma unroll
        for (int nf = 0; nf < 8; nf++) {
            int n = wn * 64 + nf * 8 + (lane & 3) * 2;
#pragma unroll
            for (int hrow = 0; hrow < 2; hrow++) {
                int mm = wm * 64 + mt * 16 + (lane >> 2) + hrow * 8;
                if (mm < rows) {
                    float b0 = bias[(size_t)e * NDIM + n0 + n];
                    float b1 = bias[(size_t)e * NDIM + n0 + n + 1];
                    float v0 = acc[mt][nf][hrow * 2 + 0] + b0;
                    float v1 = acc[mt][nf][hrow * 2 + 1] + b1;
                    if (PHASE == 1) {
                        float g0 = 0.5f * v0 * (1.f + erff(v0 * 0.70710678118654752f));
                        float g1 = 0.5f * v1 * (1.f + erff(v1 * 0.70710678118654752f));
                        *(__half2*)&g_h[(size_t)(s + mm) * HID + n0 + n] =
                            __floats2half2_rn(g0, g1);
                    } else {
                        int t = g_perm[s + mm];
                        float w = g_weight[t];
                        float2 o; o.x = w * v0; o.y = w * v1;
                        *(float2*)&out[(size_t)t * DIMSZ + n0 + n] = o;
                    }
                }
            }
        }
    }
}

// ---------------- launch ----------------
extern "C" void kernel_launch(void* const* d_in, const int* in_sizes, int n_in,
                              void* d_out, int out_size) {
    (void)in_sizes; (void)n_in; (void)out_size;
    const float* x  = (const float*)d_in[0];
    const float* wg = (const float*)d_in[1];
    const float* bg = (const float*)d_in[2];
    const float* W1 = (const float*)d_in[3];
    const float* b1 = (const float*)d_in[4];
    const float* W2 = (const float*)d_in[5];
    const float* b2 = (const float*)d_in[6];
    float* out = (float*)d_out;

    cudaFuncSetAttribute(moe_gemm<DIMSZ, HID, 1>,
                         cudaFuncAttributeMaxDynamicSharedMemorySize, SMEM_TOT);
    cudaFuncSetAttribute(moe_gemm<HID, DIMSZ, 2>,
                         cudaFuncAttributeMaxDynamicSharedMemorySize, SMEM_TOT);

    init_kernel<<<1, 32>>>();
    gate_kernel<<<N_TOK / 8, 256>>>(x, wg, bg);
    route_kernel<<<1, 256>>>();
    gather_kernel<<<N_TOK, 128>>>(x);
    moe_gemm<DIMSZ, HID, 1><<<dim3(MAX_BLK, HID / BN), 256, SMEM_TOT>>>(W1, b1, nullptr);
    moe_gemm<HID, DIMSZ, 2><<<dim3(MAX_BLK, DIMSZ / BN), 256, SMEM_TOT>>>(W2, b2, out);
}

// round 6
// speedup vs baseline: 1.0010x; 1.0010x over previous
#include <cuda_runtime.h>
#include <cuda_fp16.h>
#include <math.h>
#include <stdint.h>

#define N_TOK 4096
#define DIMSZ 1024
#define NEXP  8
#define HID   4096
#define EPSV  1e-6f
#define MAX_BLK 24        // sum ceil(c_e/256) <= 16 + 8

// tiling
#define BM   256
#define BN   128
#define KC   32
#define NSTG 3
// dynamic smem layout (bytes)
#define AS_STG   (256 * 80)          // 256 rows x 40 halves
#define BS_STG   (32 * 136 * 2)      // 32 rows x 136 halves (R0 layout)
#define BSTG_STG (32 * 528)          // 32 rows x 132 floats staging
#define OFF_AS   0
#define OFF_BS   (NSTG * AS_STG)                 // 61440
#define OFF_BSTG (OFF_BS + NSTG * BS_STG)        // 87552
#define SMEM_TOT (OFF_BSTG + NSTG * BSTG_STG)    // 138240

// ---------------- scratch ----------------
__device__ float  g_gateval[N_TOK];
__device__ int    g_expert[N_TOK];
__device__ float  g_weight[N_TOK];
__device__ float  g_denom[NEXP];
__device__ int    g_counts[NEXP];
__device__ int    g_cursor[NEXP];
__device__ int    g_perm[N_TOK];
__device__ __half g_xg[(size_t)(N_TOK + BM) * DIMSZ];  // gathered x fp16 (+pad rows, stay 0)
__device__ __half g_h[(size_t)(N_TOK + BM) * HID];     // gelu(x@W1) fp16 (+pad rows)
__device__ int    g_blk_expert[MAX_BLK];
__device__ int    g_blk_start[MAX_BLK];
__device__ int    g_blk_rows[MAX_BLK];
__device__ int    g_nblk;

__device__ __forceinline__ uint32_t s2u(const void* p) {
    return (uint32_t)__cvta_generic_to_shared(p);
}
__device__ __forceinline__ void cp16(uint32_t s, const void* g) {
    asm volatile("cp.async.cg.shared.global [%0], [%1], 16;\n" :: "r"(s), "l"(g));
}
#define CP_COMMIT() asm volatile("cp.async.commit_group;\n" ::: "memory")
#define CP_WAIT0()  asm volatile("cp.async.wait_group 0;\n" ::: "memory")
#define CP_WAIT1()  asm volatile("cp.async.wait_group 1;\n" ::: "memory")

// ---------------- kernel 0: reset ----------------
__global__ void init_kernel() {
    int t = threadIdx.x;
    if (t < NEXP) { g_denom[t] = 0.f; g_counts[t] = 0; }
}

// ---------------- kernel 1: gate ----------------
__global__ void gate_kernel(const float* __restrict__ x,
                            const float* __restrict__ wg,
                            const float* __restrict__ bg) {
    int warp = threadIdx.x >> 5, lane = threadIdx.x & 31;
    int t = blockIdx.x * 8 + warp;
    if (t >= N_TOK) return;
    const float* xr = x + (size_t)t * DIMSZ;
    float acc[NEXP];
#pragma unroll
    for (int e = 0; e < NEXP; e++) acc[e] = 0.f;
    for (int k = lane; k < DIMSZ; k += 32) {
        float xv = __ldg(xr + k);
        const float* wr = wg + (size_t)k * NEXP;
#pragma unroll
        for (int e = 0; e < NEXP; e++) acc[e] = fmaf(xv, __ldg(wr + e), acc[e]);
    }
#pragma unroll
    for (int e = 0; e < NEXP; e++)
#pragma unroll
        for (int o = 16; o > 0; o >>= 1)
            acc[e] += __shfl_xor_sync(0xFFFFFFFFu, acc[e], o);
    if (lane == 0) {
#pragma unroll
        for (int e = 0; e < NEXP; e++) acc[e] += bg[e];
        int top = 0; float best = acc[0];
#pragma unroll
        for (int e = 1; e < NEXP; e++) if (acc[e] > best) { best = acc[e]; top = e; }
        float s = 0.f;
#pragma unroll
        for (int e = 0; e < NEXP; e++) s += expf(acc[e] - best);
        float gv = 1.0f / s;
        g_gateval[t] = gv;
        g_expert[t]  = top;
        atomicAdd(&g_denom[top], gv);
        atomicAdd(&g_counts[top], 1);
    }
}

// ---------------- kernel 2: route ----------------
__global__ void route_kernel() {
    int tid = threadIdx.x;
    if (tid == 0) {
        int acc = 0, nb = 0;
        for (int e = 0; e < NEXP; e++) {
            g_cursor[e] = acc;
            int c = g_counts[e];
            for (int s = 0; s < c; s += BM) {
                g_blk_expert[nb] = e;
                g_blk_start[nb]  = acc + s;
                g_blk_rows[nb]   = min(BM, c - s);
                nb++;
            }
            acc += c;
        }
        g_nblk = nb;
    }
    __syncthreads();
    for (int t = tid; t < N_TOK; t += blockDim.x) {
        int e = g_expert[t];
        int pos = atomicAdd(&g_cursor[e], 1);
        g_perm[pos] = t;
        g_weight[t] = g_gateval[t] / (g_denom[e] + EPSV) * (float)N_TOK;
    }
}

// ---------------- kernel 3: gather ----------------
__global__ void gather_kernel(const float* __restrict__ x) {
    int i = blockIdx.x;
    int t = g_perm[i];
    const float4* src = (const float4*)(x + (size_t)t * DIMSZ);
    __half2* dst = (__half2*)(g_xg + (size_t)i * DIMSZ);
    for (int j = threadIdx.x; j < DIMSZ / 4; j += blockDim.x) {
        float4 v = src[j];
        dst[j * 2 + 0] = __floats2half2_rn(v.x, v.y);
        dst[j * 2 + 1] = __floats2half2_rn(v.z, v.w);
    }
}

// ---------------- grouped GEMM: 256x128 tile, cp.async 3-stage, mma.sync ----
// PHASE 1: A=g_xg [*,1024], B=W1 fp32 -> gelu -> g_h fp16
// PHASE 2: A=g_h  [*,4096], B=W2 fp32 -> *weight -> scatter out fp32
template <int KDIM, int NDIM, int PHASE>
__global__ void __launch_bounds__(256, 1) moe_gemm(
    const float* __restrict__ Bglob,
    const float* __restrict__ bias,
    float* __restrict__ out)
{
    int blk = blockIdx.x;
    if (blk >= g_nblk) return;
    const int e    = g_blk_expert[blk];
    const int s    = g_blk_start[blk];
    const int rows = g_blk_rows[blk];
    const int n0   = blockIdx.y * BN;

    extern __shared__ __align__(16) char dynsmem[];
    const uint32_t as_u   = s2u(dynsmem) + OFF_AS;
    const uint32_t bs_u   = s2u(dynsmem) + OFF_BS;
    const uint32_t bstg_u = s2u(dynsmem) + OFF_BSTG;

    const int tid  = threadIdx.x;
    const int warp = tid >> 5, lane = tid & 31;
    const int wm = warp >> 1;      // 0..3 -> m offset wm*64
    const int wn = warp & 1;       // 0..1 -> n offset wn*64

    const __half* A = (PHASE == 1 ? g_xg : g_h) + (size_t)s * KDIM;
    const float*  B = Bglob + (size_t)e * KDIM * NDIM + n0;

    float acc[4][8][4];
#pragma unroll
    for (int a = 0; a < 4; a++)
#pragma unroll
        for (int b = 0; b < 8; b++)
#pragma unroll
            for (int c = 0; c < 4; c++) acc[a][b][c] = 0.f;

    auto load_stage = [&](int stg, int slot) {
        const int k0 = stg * KC;
        // A: 256 rows x 32 halves = 1024 x 16B chunks
        const __half* Ap = A + k0;
#pragma unroll
        for (int it = 0; it < 4; it++) {
            int id = it * 256 + tid;
            int r = id >> 2, c = id & 3;
            cp16(as_u + slot * AS_STG + r * 80 + c * 16,
                 Ap + (size_t)r * KDIM + c * 8);
        }
        // B staging: 32 rows x 128 floats = 1024 x 16B chunks
        const float* Bp = B + (size_t)k0 * NDIM;
#pragma unroll
        for (int it = 0; it < 4; it++) {
            int id = it * 256 + tid;
            int r = id >> 5, c = id & 31;
            cp16(bstg_u + slot * BSTG_STG + r * 528 + c * 16,
                 Bp + (size_t)r * NDIM + c * 4);
        }
        CP_COMMIT();
    };

    auto convert_b = [&](int slot) {
        const float* src = (const float*)(dynsmem + OFF_BSTG + slot * BSTG_STG);
        __half* dst = (__half*)(dynsmem + OFF_BS + slot * BS_STG);
#pragma unroll
        for (int it = 0; it < 4; it++) {
            int id = it * 256 + tid;
            int r = id >> 5, c4 = id & 31;
            float4 v = *(const float4*)(src + r * 132 + c4 * 4);
            __half2* d = (__half2*)(dst + r * 136 + c4 * 4);
            d[0] = __floats2half2_rn(v.x, v.y);
            d[1] = __floats2half2_rn(v.z, v.w);
        }
    };

    // prologue
    load_stage(0, 0);
    load_stage(1, 1);

    const int nk = KDIM / KC;
    for (int k = 0; k < nk; k++) {
        const int slot = k % NSTG;
        if (k == nk - 1) { CP_WAIT0(); } else { CP_WAIT1(); }
        __syncthreads();
        convert_b(slot);
        if (k + 2 < nk) load_stage(k + 2, (k + 2) % NSTG);
        __syncthreads();

        const uint32_t abase = as_u + slot * AS_STG;
        const uint32_t bbase = bs_u + slot * BS_STG;
#pragma unroll
        for (int ks = 0; ks < 2; ks++) {
            const int kk = ks * 16;
            uint32_t afr[4][4];
#pragma unroll
            for (int mt = 0; mt < 4; mt++) {
                int r = wm * 64 + mt * 16 + (lane & 7) + ((lane >> 3) & 1) * 8;
                int c = kk + (lane >> 4) * 8;
                uint32_t addr = abase + r * 80 + c * 2;
                asm volatile("ldmatrix.sync.aligned.m8n8.x4.shared.b16 {%0,%1,%2,%3}, [%4];\n"
                             : "=r"(afr[mt][0]), "=r"(afr[mt][1]),
                               "=r"(afr[mt][2]), "=r"(afr[mt][3])
                             : "r"(addr));
            }
            uint32_t bfr[8][2];
#pragma unroll
            for (int q = 0; q < 4; q++) {
                int mi = lane >> 3;
                int kr = kk + (mi & 1) * 8 + (lane & 7);
                int nc = wn * 64 + q * 16 + (mi >> 1) * 8;
                uint32_t addr = bbase + (kr * 136 + nc) * 2;
                uint32_t r0, r1, r2, r3;
                asm volatile("ldmatrix.sync.aligned.m8n8.x4.trans.shared.b16 {%0,%1,%2,%3}, [%4];\n"
                             : "=r"(r0), "=r"(r1), "=r"(r2), "=r"(r3)
                             : "r"(addr));
                bfr[q * 2 + 0][0] = r0; bfr[q * 2 + 0][1] = r1;
                bfr[q * 2 + 1][0] = r2; bfr[q * 2 + 1][1] = r3;
            }
#pragma unroll
            for (int mt = 0; mt < 4; mt++)
#pragma unroll
                for (int nf = 0; nf < 8; nf++) {
                    asm volatile(
                        "mma.sync.aligned.m16n8k16.row.col.f32.f16.f16.f32 "
                        "{%0,%1,%2,%3}, {%4,%5,%6,%7}, {%8,%9}, {%0,%1,%2,%3};\n"
                        : "+f"(acc[mt][nf][0]), "+f"(acc[mt][nf][1]),
                          "+f"(acc[mt][nf][2]), "+f"(acc[mt][nf][3])
                        : "r"(afr[mt][0]), "r"(afr[mt][1]),
                          "r"(afr[mt][2]), "r"(afr[mt][3]),
                          "r"(bfr[nf][0]), "r"(bfr[nf][1]));
                }
        }
        __syncthreads();
    }

    // ---------------- epilogue ----------------
#pragma unroll
    for (int mt = 0; mt < 4; mt++) {
#pragma unroll
        for (int nf = 0; nf < 8; nf++) {
            int n = wn * 64 + nf * 8 + (lane & 3) * 2;
#pragma unroll
            for (int hrow = 0; hrow < 2; hrow++) {
                int mm = wm * 64 + mt * 16 + (lane >> 2) + hrow * 8;
                if (mm < rows) {
                    float b0 = bias[(size_t)e * NDIM + n0 + n];
                    float b1 = bias[(size_t)e * NDIM + n0 + n + 1];
                    float v0 = acc[mt][nf][hrow * 2 + 0] + b0;
                    float v1 = acc[mt][nf][hrow * 2 + 1] + b1;
                    if (PHASE == 1) {
                        float g0 = 0.5f * v0 * (1.f + erff(v0 * 0.70710678118654752f));
                        float g1 = 0.5f * v1 * (1.f + erff(v1 * 0.70710678118654752f));
                        *(__half2*)&g_h[(size_t)(s + mm) * HID + n0 + n] =
                            __floats2half2_rn(g0, g1);
                    } else {
                        int t = g_perm[s + mm];
                        float w = g_weight[t];
                        float2 o; o.x = w * v0; o.y = w * v1;
                        *(float2*)&out[(size_t)t * DIMSZ + n0 + n] = o;
                    }
                }
            }
        }
    }
}

// ---------------- launch ----------------
extern "C" void kernel_launch(void* const* d_in, const int* in_sizes, int n_in,
                              void* d_out, int out_size) {
    (void)in_sizes; (void)n_in; (void)out_size;
    const float* x  = (const float*)d_in[0];
    const float* wg = (const float*)d_in[1];
    const float* bg = (const float*)d_in[2];
    const float* W1 = (const float*)d_in[3];
    const float* b1 = (const float*)d_in[4];
    const float* W2 = (const float*)d_in[5];
    const float* b2 = (const float*)d_in[6];
    float* out = (float*)d_out;

    cudaFuncSetAttribute(moe_gemm<DIMSZ, HID, 1>,
                         cudaFuncAttributeMaxDynamicSharedMemorySize, SMEM_TOT);
    cudaFuncSetAttribute(moe_gemm<HID, DIMSZ, 2>,
                         cudaFuncAttributeMaxDynamicSharedMemorySize, SMEM_TOT);

    init_kernel<<<1, 32>>>();
    gate_kernel<<<N_TOK / 8, 256>>>(x, wg, bg);
    route_kernel<<<1, 256>>>();
    gather_kernel<<<N_TOK, 128>>>(x);
    moe_gemm<DIMSZ, HID, 1><<<dim3(MAX_BLK, HID / BN), 256, SMEM_TOT>>>(W1, b1, nullptr);
    moe_gemm<HID, DIMSZ, 2><<<dim3(MAX_BLK, DIMSZ / BN), 256, SMEM_TOT>>>(W2, b2, out);
}